// round 1
// baseline (speedup 1.0000x reference)
#include <cuda_runtime.h>

// ConvQuadInterp3d: 3x3x3 stencil refinement over x:(B=2,C=1,D=8,H=512,W=512) fp32.
// Output buffer = coords_max (B,1,3,D,H,W) flattened, then y_max (B,1,D,H,W).

#define Dd 8
#define Hh 512
#define Ww 512
#define Bb 2
#define PLANE (Hh * Ww)

__device__ __forceinline__ void load_plane(const float* __restrict__ x, int base,
                                           int hm, int h0, int hp,
                                           int wm, int w0, int wp, float* p) {
    const float* r0 = x + base + hm * Ww;
    const float* r1 = x + base + h0 * Ww;
    const float* r2 = x + base + hp * Ww;
    p[0] = __ldg(r0 + wm); p[1] = __ldg(r0 + w0); p[2] = __ldg(r0 + wp);
    p[3] = __ldg(r1 + wm); p[4] = __ldg(r1 + w0); p[5] = __ldg(r1 + wp);
    p[6] = __ldg(r2 + wm); p[7] = __ldg(r2 + w0); p[8] = __ldg(r2 + wp);
}

__global__ void __launch_bounds__(256)
conv_quad_interp3d_kernel(const float* __restrict__ x, float* __restrict__ out) {
    const int w = blockIdx.x * 64 + threadIdx.x;
    const int h = blockIdx.y * 4 + threadIdx.y;
    const int b = blockIdx.z;

    const int wm = max(w - 1, 0), wp = min(w + 1, Ww - 1);
    const int hm = max(h - 1, 0), hp = min(h + 1, Hh - 1);
    const int xbase = b * Dd * PLANE;

    // Rolling 3-plane 3x3 register window: P0 = plane d-1, P1 = d, P2 = d+1 (clamped).
    float P0[9], P1[9], P2[9];
    load_plane(x, xbase + 0 * PLANE, hm, h, hp, wm, w, wp, P1);
#pragma unroll
    for (int i = 0; i < 9; i++) P0[i] = P1[i];   // replicate pad at d = -1
    load_plane(x, xbase + 1 * PLANE, hm, h, hp, wm, w, wp, P2);

    const int hw = h * Ww + w;
    float* coordsD = out + (b * 3 + 0) * Dd * PLANE;
    float* coordsW = out + (b * 3 + 1) * Dd * PLANE;
    float* coordsH = out + (b * 3 + 2) * Dd * PLANE;
    float* ymax    = out + Bb * 3 * Dd * PLANE + b * Dd * PLANE;

#pragma unroll
    for (int d = 0; d < Dd; d++) {
        const float c = P1[4];

        // First-order central differences (replicate pad), b = [gx(gW), gy(gH), gs(gD)]
        const float gx = 0.5f * (P1[5] - P1[3]);
        const float gy = 0.5f * (P1[7] - P1[1]);
        const float gs = 0.5f * (P2[4] - P0[4]);

        // Second-order terms (cross terms scaled by 0.25 as in the reference)
        const float axx = P1[3] + P1[5] - 2.0f * c;
        const float ayy = P1[1] + P1[7] - 2.0f * c;
        const float ass = P0[4] + P2[4] - 2.0f * c;
        const float axy = 0.25f * (P1[0] + P1[8] - P1[6] - P1[2]);
        const float ays = 0.25f * (P0[1] + P2[7] - P2[1] - P0[7]);
        const float axs = 0.25f * (P0[3] + P2[5] - P2[3] - P0[5]);

        // NMS: x == maxpool3d(x,3) with -inf pad == max over valid (clamped dup-safe) 27
        float m = c;
#pragma unroll
        for (int i = 0; i < 9; i++) {
            m = fmaxf(m, P0[i]); m = fmaxf(m, P1[i]); m = fmaxf(m, P2[i]);
        }
        const bool nms = (c == m);

        // Symmetric 3x3 det (first-row cofactor expansion)
        const float c00 = ayy * ass - ays * ays;
        const float c01 = axs * ays - axy * ass;
        const float c02 = axy * ays - axs * ayy;
        const float det = axx * c00 + axy * c01 + axs * c02;

        const bool keep = nms && (det != 0.0f);

        float rx = 0.0f, ry = 0.0f, rs = 0.0f;
        if (keep) {
            const float inv = 1.0f / det;
            const float c11 = axx * ass - axs * axs;
            const float c12 = axy * axs - axx * ays;
            const float c22 = axx * ayy - axy * axy;
            const float sx = (c00 * gx + c01 * gy + c02 * gs) * inv;
            const float sy = (c01 * gx + c11 * gy + c12 * gs) * inv;
            const float ss = (c02 * gx + c12 * gy + c22 * gs) * inv;
            rx = -sx; ry = -sy; rs = -ss;
            const float big = fmaxf(fabsf(rx), fmaxf(fabsf(ry), fabsf(rs)));
            if (big > 0.7f) { rx = 0.0f; ry = 0.0f; rs = 0.0f; }
        }

        const float dyv = 0.5f * (gx * rx + gy * ry + gs * rs);
        const float y = c + dyv + (keep ? 10.0f : 0.0f);

        // coords channels: grid(d, w, h) + refinement(s, y, x)  [kornia's exact ordering]
        const int dhw = d * PLANE + hw;
        coordsD[dhw] = (float)d + rs;
        coordsW[dhw] = (float)w + ry;
        coordsH[dhw] = (float)h + rx;
        ymax[dhw]    = y;

        if (d < Dd - 1) {
#pragma unroll
            for (int i = 0; i < 9; i++) { P0[i] = P1[i]; P1[i] = P2[i]; }
            const int dn = min(d + 2, Dd - 1);
            load_plane(x, xbase + dn * PLANE, hm, h, hp, wm, w, wp, P2);
        }
    }
}

extern "C" void kernel_launch(void* const* d_in, const int* in_sizes, int n_in,
                              void* d_out, int out_size) {
    const float* x = (const float*)d_in[0];
    float* out = (float*)d_out;
    dim3 block(64, 4, 1);
    dim3 grid(Ww / 64, Hh / 4, Bb);
    conv_quad_interp3d_kernel<<<grid, block>>>(x, out);
}